// round 3
// baseline (speedup 1.0000x reference)
#include <cuda_runtime.h>
#include <math.h>

#define HW     3600
#define NB     2
#define CK     3072      // 2048 + 1024 stacked channels
#define C4     2048
#define C3     1024
#define CQ     256
#define TEMP   20.0f
#define ATT_WT 0.5f
#define EPS    1e-12f

#define SZ3    (NB * C3 * HW)   // 7,372,800
#define SZ4    (NB * C4 * HW)   // 14,745,600
#define SZQ    (NB * CQ * HW)   // 1,843,200

// ---------------- scratch (static device arrays: allocation-free) -----------
__device__ float g_A[(size_t)NB * CK * HW];     // normalized query feats   [b][k][q]
__device__ float g_B[(size_t)NB * CK * HW];     // normalized support feats [b][k][s]
__device__ float g_corr[(size_t)NB * HW * HW];  // corr / attn              [b][q][s]
__device__ float g_att[(size_t)NB * CQ * HW];   // att_fq                   [b][c][q]

// ---------------- 1) channel L2 normalize into stacked buffer ---------------
// NOTE: output buffer selected IN DEVICE CODE (never pass __device__ symbols
// from host — on GB300/ATS that silently writes host memory instead).
__global__ void normalize_kernel(const float* __restrict__ in, int Cf, int coff, int sel) {
    float* out = sel ? g_B : g_A;
    int blk = blockIdx.x;                 // 0 .. 2*57-1
    int b   = blk / 57;
    int p0  = (blk % 57) * 64;
    int tid = threadIdx.x;
    int cg  = tid >> 6;                   // 0..3
    int pl  = tid & 63;
    int p   = p0 + pl;
    bool valid = (p < HW);

    const float* base = in + ((size_t)b * Cf) * HW + p;
    float ss = 0.f;
    if (valid) {
        #pragma unroll 8
        for (int c = cg; c < Cf; c += 4) {
            float v = base[(size_t)c * HW];
            ss += v * v;
        }
    }
    __shared__ float part[4][64];
    __shared__ float sinv[64];
    part[cg][pl] = ss;
    __syncthreads();
    if (tid < 64) {
        float t = part[0][tid] + part[1][tid] + part[2][tid] + part[3][tid];
        sinv[tid] = 1.f / fmaxf(sqrtf(t), EPS);
    }
    __syncthreads();
    float inv = sinv[pl];
    float* ob = out + ((size_t)b * CK + coff) * HW + p;
    if (valid) {
        #pragma unroll 8
        for (int c = cg; c < Cf; c += 4)
            ob[(size_t)c * HW] = base[(size_t)c * HW] * inv;
    }
}

// ---------------- 2) corr GEMM: corr[b][q][s] = 0.5 * sum_k A[k][q]*B[k][s] --
__global__ __launch_bounds__(256, 2)
void gemm_corr_kernel() {
    const int BM = 128, BN = 128, BK = 16;
    int n0 = blockIdx.x * BN;
    int m0 = blockIdx.y * BM;
    int b  = blockIdx.z;

    const float* Ab = g_A + (size_t)b * CK * HW;
    const float* Bb = g_B + (size_t)b * CK * HW;
    float*       Cb = g_corr + (size_t)b * HW * HW;

    __shared__ float As[BK][BM];
    __shared__ float Bs[BK][BN];

    int tid = threadIdx.x;
    int ty = tid >> 4;      // 0..15
    int tx = tid & 15;      // 0..15

    float acc[8][8];
    #pragma unroll
    for (int i = 0; i < 8; i++)
        #pragma unroll
        for (int j = 0; j < 8; j++) acc[i][j] = 0.f;

    for (int k0 = 0; k0 < CK; k0 += BK) {
        #pragma unroll
        for (int i = 0; i < 2; i++) {
            int f  = tid + i * 256;          // 0..511 float4 slots
            int kr = f >> 5;                 // 0..15
            int mc = (f & 31) << 2;          // 0..124
            float4 va = make_float4(0.f, 0.f, 0.f, 0.f);
            float4 vb = make_float4(0.f, 0.f, 0.f, 0.f);
            if (m0 + mc < HW)
                va = *(const float4*)&Ab[(size_t)(k0 + kr) * HW + m0 + mc];
            if (n0 + mc < HW)
                vb = *(const float4*)&Bb[(size_t)(k0 + kr) * HW + n0 + mc];
            *(float4*)&As[kr][mc] = va;
            *(float4*)&Bs[kr][mc] = vb;
        }
        __syncthreads();

        #pragma unroll
        for (int kk = 0; kk < BK; kk++) {
            float a[8], bb[8];
            *(float4*)(a)     = *(float4*)&As[kk][ty * 8];
            *(float4*)(a + 4) = *(float4*)&As[kk][ty * 8 + 4];
            *(float4*)(bb)    = *(float4*)&Bs[kk][tx * 8];
            *(float4*)(bb + 4)= *(float4*)&Bs[kk][tx * 8 + 4];
            #pragma unroll
            for (int i = 0; i < 8; i++)
                #pragma unroll
                for (int j = 0; j < 8; j++)
                    acc[i][j] += a[i] * bb[j];
        }
        __syncthreads();
    }

    #pragma unroll
    for (int i = 0; i < 8; i++) {
        int m = m0 + ty * 8 + i;
        if (m >= HW) continue;
        #pragma unroll
        for (int j4 = 0; j4 < 8; j4 += 4) {
            int n = n0 + tx * 8 + j4;
            if (n < HW) {
                float4 v = make_float4(0.5f * acc[i][j4], 0.5f * acc[i][j4 + 1],
                                       0.5f * acc[i][j4 + 2], 0.5f * acc[i][j4 + 3]);
                *(float4*)&Cb[(size_t)m * HW + n] = v;
            }
        }
    }
}

// ---------------- 3) row softmax (temp 20), in place -------------------------
__device__ __forceinline__ float warpRedMax(float v) {
    #pragma unroll
    for (int o = 16; o; o >>= 1) v = fmaxf(v, __shfl_xor_sync(0xffffffffu, v, o));
    return v;
}
__device__ __forceinline__ float warpRedSum(float v) {
    #pragma unroll
    for (int o = 16; o; o >>= 1) v += __shfl_xor_sync(0xffffffffu, v, o);
    return v;
}

__global__ void softmax_kernel() {
    int row = blockIdx.x;                          // 0 .. NB*HW-1
    float* base = g_corr + (size_t)row * HW;
    int tid = threadIdx.x;
    __shared__ float red[8];

    float v[15];
    float mx = -1e30f;
    #pragma unroll
    for (int i = 0; i < 15; i++) {
        int s = tid + i * 256;
        v[i] = (s < HW) ? base[s] * TEMP : -1e30f;
        mx = fmaxf(mx, v[i]);
    }
    mx = warpRedMax(mx);
    if ((tid & 31) == 0) red[tid >> 5] = mx;
    __syncthreads();
    if (tid < 32) {
        float t = (tid < 8) ? red[tid] : -1e30f;
        t = warpRedMax(t);
        if (tid == 0) red[0] = t;
    }
    __syncthreads();
    mx = red[0];
    __syncthreads();

    float sum = 0.f;
    #pragma unroll
    for (int i = 0; i < 15; i++) {
        int s = tid + i * 256;
        float e = (s < HW) ? expf(v[i] - mx) : 0.f;
        v[i] = e;
        sum += e;
    }
    sum = warpRedSum(sum);
    if ((tid & 31) == 0) red[tid >> 5] = sum;
    __syncthreads();
    if (tid < 32) {
        float t = (tid < 8) ? red[tid] : 0.f;
        t = warpRedSum(t);
        if (tid == 0) red[0] = t;
    }
    __syncthreads();
    float r = 1.f / red[0];

    #pragma unroll
    for (int i = 0; i < 15; i++) {
        int s = tid + i * 256;
        if (s < HW) base[s] = v[i] * r;
    }
}

// ---------------- 4) attention GEMM: att[b][c][q] = sum_s attn[q][s]*V[c][s] -
__global__ __launch_bounds__(256, 2)
void gemm_att_kernel(const float* __restrict__ V) {
    const int BM = 128, BN = 128, BK = 16;
    int q0 = blockIdx.x * BN;
    int c0 = blockIdx.y * BM;
    int b  = blockIdx.z;

    const float* Vb = V + (size_t)b * CQ * HW;
    const float* Tb = g_corr + (size_t)b * HW * HW;
    float*       Ob = g_att + (size_t)b * CQ * HW;

    __shared__ float As[BK][BM + 4];   // V^T   : As[s][c]
    __shared__ float Bs[BK][BN + 4];   // attn^T: Bs[s][q]

    int tid = threadIdx.x;
    int ty = tid >> 4;
    int tx = tid & 15;

    float acc[8][8];
    #pragma unroll
    for (int i = 0; i < 8; i++)
        #pragma unroll
        for (int j = 0; j < 8; j++) acc[i][j] = 0.f;

    for (int s0 = 0; s0 < HW; s0 += BK) {
        #pragma unroll
        for (int i = 0; i < 2; i++) {
            int f   = tid + i * 256;      // 0..511
            int row = f >> 2;             // 0..127
            int sc  = (f & 3) << 2;       // 0,4,8,12
            float4 va = *(const float4*)&Vb[(size_t)(c0 + row) * HW + s0 + sc];
            As[sc + 0][row] = va.x;
            As[sc + 1][row] = va.y;
            As[sc + 2][row] = va.z;
            As[sc + 3][row] = va.w;
            float4 vb = make_float4(0.f, 0.f, 0.f, 0.f);
            if (q0 + row < HW)
                vb = *(const float4*)&Tb[(size_t)(q0 + row) * HW + s0 + sc];
            Bs[sc + 0][row] = vb.x;
            Bs[sc + 1][row] = vb.y;
            Bs[sc + 2][row] = vb.z;
            Bs[sc + 3][row] = vb.w;
        }
        __syncthreads();

        #pragma unroll
        for (int kk = 0; kk < BK; kk++) {
            float a[8], bb[8];
            *(float4*)(a)      = *(float4*)&As[kk][ty * 8];
            *(float4*)(a + 4)  = *(float4*)&As[kk][ty * 8 + 4];
            *(float4*)(bb)     = *(float4*)&Bs[kk][tx * 8];
            *(float4*)(bb + 4) = *(float4*)&Bs[kk][tx * 8 + 4];
            #pragma unroll
            for (int i = 0; i < 8; i++)
                #pragma unroll
                for (int j = 0; j < 8; j++)
                    acc[i][j] += a[i] * bb[j];
        }
        __syncthreads();
    }

    #pragma unroll
    for (int i = 0; i < 8; i++) {
        int c = c0 + ty * 8 + i;          // always < 256
        #pragma unroll
        for (int j4 = 0; j4 < 8; j4 += 4) {
            int q = q0 + tx * 8 + j4;
            if (q < HW) {
                float4 v = make_float4(acc[i][j4], acc[i][j4 + 1],
                                       acc[i][j4 + 2], acc[i][j4 + 3]);
                *(float4*)&Ob[(size_t)c * HW + q] = v;
            }
        }
    }
}

// ---------------- 5) fq = l2norm(f_q) + 0.5 * l2norm(att_fq) ----------------
__global__ void combine_kernel(const float* __restrict__ f_q,
                               float* __restrict__ out_fq) {
    int idx = blockIdx.x * blockDim.x + threadIdx.x;
    if (idx >= NB * HW) return;
    int b = idx / HW, p = idx % HW;
    const float* qb = f_q + (size_t)b * CQ * HW + p;
    const float* ab = g_att + (size_t)b * CQ * HW + p;
    float sq = 0.f, sa = 0.f;
    #pragma unroll 8
    for (int c = 0; c < CQ; c++) {
        float x = qb[(size_t)c * HW]; sq += x * x;
        float y = ab[(size_t)c * HW]; sa += y * y;
    }
    float iq = 1.f / fmaxf(sqrtf(sq), EPS);
    float ia = ATT_WT / fmaxf(sqrtf(sa), EPS);
    float* ob = out_fq + (size_t)b * CQ * HW + p;
    #pragma unroll 8
    for (int c = 0; c < CQ; c++)
        ob[(size_t)c * HW] = qb[(size_t)c * HW] * iq + ab[(size_t)c * HW] * ia;
}

// ---------------- 6) copy att_fq scratch into second output slot -------------
__global__ void copy_att_kernel(float* __restrict__ dst) {
    int i = blockIdx.x * blockDim.x + threadIdx.x;
    int n4 = SZQ / 4;
    if (i < n4)
        ((float4*)dst)[i] = ((const float4*)g_att)[i];
}

// ---------------- launch -----------------------------------------------------
extern "C" void kernel_launch(void* const* d_in, const int* in_sizes, int n_in,
                              void* d_out, int out_size) {
    // Identify inputs by element count (robust to metadata ordering):
    // 7,372,800 -> {fq3, fs3}; 14,745,600 -> {fq4, fs4}; 1,843,200 -> {f_q, f_s}
    const float *fq3 = 0, *fs3 = 0, *fq4 = 0, *fs4 = 0, *f_q = 0, *f_s = 0;
    for (int i = 0; i < n_in; i++) {
        const float* p = (const float*)d_in[i];
        int sz = in_sizes[i];
        if (sz == SZ3)      { if (!fq3) fq3 = p; else fs3 = p; }
        else if (sz == SZ4) { if (!fq4) fq4 = p; else fs4 = p; }
        else if (sz == SZQ) { if (!f_q) f_q = p; else f_s = p; }
    }
    float* out = (float*)d_out;

    normalize_kernel<<<114, 256>>>(fq4, C4, 0, 0);   // -> g_A[0:2048)
    normalize_kernel<<<114, 256>>>(fs4, C4, 0, 1);   // -> g_B[0:2048)
    normalize_kernel<<<114, 256>>>(fq3, C3, C4, 0);  // -> g_A[2048:3072)
    normalize_kernel<<<114, 256>>>(fs3, C3, C4, 1);  // -> g_B[2048:3072)

    gemm_corr_kernel<<<dim3(29, 29, NB), 256>>>();

    softmax_kernel<<<NB * HW, 256>>>();

    gemm_att_kernel<<<dim3(29, 2, NB), 256>>>(f_s);

    combine_kernel<<<29, 256>>>(f_q, out);

    if (out_size >= 2 * SZQ) {
        copy_att_kernel<<<(SZQ / 4 + 255) / 256, 256>>>(out + SZQ);
    }
}

// round 5
// speedup vs baseline: 2.4445x; 2.4445x over previous
#include <cuda_runtime.h>
#include <cstdint>
#include <math.h>

#define HW     3600
#define NB     2
#define CK     3072      // 2048 + 1024 stacked channels
#define C4     2048
#define C3     1024
#define CQ     256
#define TEMP   20.0f
#define ATT_WT 0.5f
#define EPS    1e-12f

#define SZ3    (NB * C3 * HW)   // 7,372,800
#define SZ4    (NB * C4 * HW)   // 14,745,600
#define SZQ    (NB * CQ * HW)   // 1,843,200

// ---------------- scratch (static device arrays: allocation-free) -----------
__device__ float g_At[(size_t)NB * HW * CK];    // normalized q feats, K-major tf32 [b][m][k]
__device__ float g_Bt[(size_t)NB * HW * CK];    // normalized s feats, K-major tf32 [b][n][k]
__device__ float g_corr[(size_t)NB * HW * HW];  // corr / attn  [b][q][s]
__device__ float g_att[(size_t)NB * CQ * HW];   // att_fq       [b][c][q]
__device__ float g_inv[4 * NB * HW];            // inv norms: 0=q4 1=s4 2=q3 3=s3

__device__ __forceinline__ uint32_t smem_u32(const void* p) {
    uint32_t a;
    asm("{ .reg .u64 t; cvta.to.shared.u64 t, %1; cvt.u32.u64 %0, t; }" : "=r"(a) : "l"(p));
    return a;
}

// ---------------- 1a) per-pixel inv L2 norms ---------------------------------
__global__ void norms_kernel(const float* __restrict__ in, int Cf, int sel) {
    int blk = blockIdx.x;                 // 0 .. 2*57-1
    int b   = blk / 57;
    int p0  = (blk % 57) * 64;
    int tid = threadIdx.x;
    int cg  = tid >> 6;
    int pl  = tid & 63;
    int p   = p0 + pl;
    bool valid = (p < HW);

    const float* base = in + ((size_t)b * Cf) * HW + p;
    float ss = 0.f;
    if (valid) {
        #pragma unroll 8
        for (int c = cg; c < Cf; c += 4) {
            float v = base[(size_t)c * HW];
            ss += v * v;
        }
    }
    __shared__ float part[4][64];
    part[cg][pl] = ss;
    __syncthreads();
    if (tid < 64 && p0 + tid < HW) {
        float t = part[0][tid] + part[1][tid] + part[2][tid] + part[3][tid];
        g_inv[(size_t)sel * NB * HW + (size_t)b * HW + p0 + tid] = 1.f / fmaxf(sqrtf(t), EPS);
    }
}

// ---------------- 1b) scale + transpose + tf32-round into K-major ------------
__global__ void transpose_kernel(const float* __restrict__ in, int Cf, int coff,
                                 int sel /*0=A 1=B*/, int inv_sel) {
    __shared__ float t[32][33];
    int b  = blockIdx.z;
    int c0 = blockIdx.y * 32;
    int p0 = blockIdx.x * 32;
    int tx = threadIdx.x, ty = threadIdx.y;   // 32 x 8

    const float* X = in + (size_t)b * Cf * HW;
    float* T = (sel ? g_Bt : g_At) + (size_t)b * HW * CK;
    const float* inv = g_inv + (size_t)inv_sel * NB * HW + (size_t)b * HW;

    #pragma unroll
    for (int j = 0; j < 4; j++) {
        int c = c0 + ty + 8 * j;
        int p = p0 + tx;
        t[ty + 8 * j][tx] = (p < HW) ? X[(size_t)c * HW + p] : 0.f;
    }
    __syncthreads();
    #pragma unroll
    for (int j = 0; j < 4; j++) {
        int p = p0 + ty + 8 * j;
        if (p < HW) {
            float v = t[tx][ty + 8 * j] * inv[p];
            uint32_t u;
            asm("cvt.rna.tf32.f32 %0, %1;" : "=r"(u) : "f"(v));
            T[(size_t)p * CK + coff + c0 + tx] = __uint_as_float(u);
        }
    }
}

// ---------------- 2) corr GEMM via legacy mma.sync tf32 ----------------------
// CTA tile 128x128x32, 8 warps (4x2), warp tile 32x64, 2-stage cp.async.
#define TK        32
#define SROW      36                         // padded row stride (floats)
#define STAGE_F   (128 * SROW)               // 4608 floats per operand stage
#define GEMM_SMEM (4 * STAGE_F * 4)          // A[2]+B[2] stages = 73728 B

__device__ __forceinline__ void mma_tf32(float* d, const uint32_t* a, const uint32_t* b) {
    asm volatile(
        "mma.sync.aligned.m16n8k8.row.col.f32.tf32.tf32.f32 "
        "{%0,%1,%2,%3}, {%4,%5,%6,%7}, {%8,%9}, {%0,%1,%2,%3};"
        : "+f"(d[0]), "+f"(d[1]), "+f"(d[2]), "+f"(d[3])
        : "r"(a[0]), "r"(a[1]), "r"(a[2]), "r"(a[3]), "r"(b[0]), "r"(b[1]));
}

__global__ __launch_bounds__(256, 2) void gemm_corr_mma() {
    extern __shared__ float sm[];
    uint32_t sbase = smem_u32(sm);
    int tid  = threadIdx.x;
    int wid  = tid >> 5, lane = tid & 31;
    int grp  = lane >> 2, tig = lane & 3;
    int wm   = (wid & 3) * 32;
    int wn   = (wid >> 2) * 64;
    int b    = blockIdx.z;
    int m0   = blockIdx.y * 128;
    int n0   = blockIdx.x * 128;
    const float* At = g_At + (size_t)b * HW * CK;
    const float* Bt = g_Bt + (size_t)b * HW * CK;

    float acc[2][8][4];
    #pragma unroll
    for (int mi = 0; mi < 2; mi++)
        #pragma unroll
        for (int ni = 0; ni < 8; ni++)
            #pragma unroll
            for (int j = 0; j < 4; j++) acc[mi][ni][j] = 0.f;

    // ---- async tile loader: stage s gets k-chunk `iter` --------------------
    auto load_tile = [&](int iter, int s) {
        int k0 = iter * TK;
        #pragma unroll
        for (int j = 0; j < 4; j++) {
            int f   = tid + j * 256;        // 0..1023
            int row = f >> 3;
            int q   = f & 7;                // k sub = q*4
            // A
            {
                uint32_t nb = (m0 + row < HW) ? 16u : 0u;
                const float* gp = At + (size_t)(m0 + (nb ? row : 0)) * CK + k0 + q * 4;
                uint32_t sa = sbase + (s * STAGE_F + row * SROW + q * 4) * 4;
                asm volatile("cp.async.cg.shared.global [%0], [%1], 16, %2;"
                             :: "r"(sa), "l"(gp), "r"(nb) : "memory");
            }
            // B
            {
                uint32_t nb = (n0 + row < HW) ? 16u : 0u;
                const float* gp = Bt + (size_t)(n0 + (nb ? row : 0)) * CK + k0 + q * 4;
                uint32_t sa = sbase + ((2 + s) * STAGE_F + row * SROW + q * 4) * 4;
                asm volatile("cp.async.cg.shared.global [%0], [%1], 16, %2;"
                             :: "r"(sa), "l"(gp), "r"(nb) : "memory");
            }
        }
        asm volatile("cp.async.commit_group;" ::: "memory");
    };

    load_tile(0, 0);
    load_tile(1, 1);

    const int NIT = CK / TK;   // 96
    for (int i = 0; i < NIT; i++) {
        int s = i & 1;
        asm volatile("cp.async.wait_group 1;" ::: "memory");
        __syncthreads();

        const float* as = sm + s * STAGE_F;
        const float* bs = sm + (2 + s) * STAGE_F;
        #pragma unroll
        for (int ks = 0; ks < 4; ks++) {
            int kk = ks * 8;
            uint32_t af[2][4];
            #pragma unroll
            for (int mi = 0; mi < 2; mi++) {
                int r = wm + mi * 16 + grp;
                af[mi][0] = __float_as_uint(as[r * SROW + kk + tig]);
                af[mi][1] = __float_as_uint(as[(r + 8) * SROW + kk + tig]);
                af[mi][2] = __float_as_uint(as[r * SROW + kk + tig + 4]);
                af[mi][3] = __float_as_uint(as[(r + 8) * SROW + kk + tig + 4]);
            }
            uint32_t bf[8][2];
            #pragma unroll
            for (int ni = 0; ni < 8; ni++) {
                int r = wn + ni * 8 + grp;
                bf[ni][0] = __float_as_uint(bs[r * SROW + kk + tig]);
                bf[ni][1] = __float_as_uint(bs[r * SROW + kk + tig + 4]);
            }
            #pragma unroll
            for (int mi = 0; mi < 2; mi++)
                #pragma unroll
                for (int ni = 0; ni < 8; ni++)
                    mma_tf32(acc[mi][ni], af[mi], bf[ni]);
        }
        __syncthreads();
        if (i + 2 < NIT) load_tile(i + 2, s);
    }

    // ---- epilogue: 0.5 * acc -> g_corr --------------------------------------
    float* Cb = g_corr + (size_t)b * HW * HW;
    #pragma unroll
    for (int mi = 0; mi < 2; mi++) {
        int mrow = m0 + wm + mi * 16 + grp;
        #pragma unroll
        for (int ni = 0; ni < 8; ni++) {
            int n = n0 + wn + ni * 8 + 2 * tig;
            if (n < HW) {
                if (mrow < HW) {
                    float2 v = make_float2(0.5f * acc[mi][ni][0], 0.5f * acc[mi][ni][1]);
                    *(float2*)&Cb[(size_t)mrow * HW + n] = v;
                }
                if (mrow + 8 < HW) {
                    float2 v = make_float2(0.5f * acc[mi][ni][2], 0.5f * acc[mi][ni][3]);
                    *(float2*)&Cb[(size_t)(mrow + 8) * HW + n] = v;
                }
            }
        }
    }
}

// ---------------- 3) row softmax (temp 20), in place -------------------------
__device__ __forceinline__ float warpRedMax(float v) {
    #pragma unroll
    for (int o = 16; o; o >>= 1) v = fmaxf(v, __shfl_xor_sync(0xffffffffu, v, o));
    return v;
}
__device__ __forceinline__ float warpRedSum(float v) {
    #pragma unroll
    for (int o = 16; o; o >>= 1) v += __shfl_xor_sync(0xffffffffu, v, o);
    return v;
}

__global__ void softmax_kernel() {
    int row = blockIdx.x;
    float* base = g_corr + (size_t)row * HW;
    int tid = threadIdx.x;
    __shared__ float red[8];

    float v[15];
    float mx = -1e30f;
    #pragma unroll
    for (int i = 0; i < 15; i++) {
        int s = tid + i * 256;
        v[i] = (s < HW) ? base[s] * TEMP : -1e30f;
        mx = fmaxf(mx, v[i]);
    }
    mx = warpRedMax(mx);
    if ((tid & 31) == 0) red[tid >> 5] = mx;
    __syncthreads();
    if (tid < 32) {
        float t = (tid < 8) ? red[tid] : -1e30f;
        t = warpRedMax(t);
        if (tid == 0) red[0] = t;
    }
    __syncthreads();
    mx = red[0];
    __syncthreads();

    float sum = 0.f;
    #pragma unroll
    for (int i = 0; i < 15; i++) {
        int s = tid + i * 256;
        float e = (s < HW) ? expf(v[i] - mx) : 0.f;
        v[i] = e;
        sum += e;
    }
    sum = warpRedSum(sum);
    if ((tid & 31) == 0) red[tid >> 5] = sum;
    __syncthreads();
    if (tid < 32) {
        float t = (tid < 8) ? red[tid] : 0.f;
        t = warpRedSum(t);
        if (tid == 0) red[0] = t;
    }
    __syncthreads();
    float r = 1.f / red[0];

    #pragma unroll
    for (int i = 0; i < 15; i++) {
        int s = tid + i * 256;
        if (s < HW) base[s] = v[i] * r;
    }
}

// ---------------- 4) attention GEMM (fp32): att[b][c][q]=sum_s attn[q][s]V[c][s]
__global__ __launch_bounds__(256, 2)
void gemm_att_kernel(const float* __restrict__ V) {
    const int BM = 128, BN = 128, BK = 16;
    int q0 = blockIdx.x * BN;
    int c0 = blockIdx.y * BM;
    int b  = blockIdx.z;

    const float* Vb = V + (size_t)b * CQ * HW;
    const float* Tb = g_corr + (size_t)b * HW * HW;
    float*       Ob = g_att + (size_t)b * CQ * HW;

    __shared__ float As[BK][BM + 4];
    __shared__ float Bs[BK][BN + 4];

    int tid = threadIdx.x;
    int ty = tid >> 4;
    int tx = tid & 15;

    float acc[8][8];
    #pragma unroll
    for (int i = 0; i < 8; i++)
        #pragma unroll
        for (int j = 0; j < 8; j++) acc[i][j] = 0.f;

    for (int s0 = 0; s0 < HW; s0 += BK) {
        #pragma unroll
        for (int i = 0; i < 2; i++) {
            int f   = tid + i * 256;
            int row = f >> 2;
            int sc  = (f & 3) << 2;
            float4 va = *(const float4*)&Vb[(size_t)(c0 + row) * HW + s0 + sc];
            As[sc + 0][row] = va.x;
            As[sc + 1][row] = va.y;
            As[sc + 2][row] = va.z;
            As[sc + 3][row] = va.w;
            float4 vb = make_float4(0.f, 0.f, 0.f, 0.f);
            if (q0 + row < HW)
                vb = *(const float4*)&Tb[(size_t)(q0 + row) * HW + s0 + sc];
            Bs[sc + 0][row] = vb.x;
            Bs[sc + 1][row] = vb.y;
            Bs[sc + 2][row] = vb.z;
            Bs[sc + 3][row] = vb.w;
        }
        __syncthreads();

        #pragma unroll
        for (int kk = 0; kk < BK; kk++) {
            float a[8], bb[8];
            *(float4*)(a)      = *(float4*)&As[kk][ty * 8];
            *(float4*)(a + 4)  = *(float4*)&As[kk][ty * 8 + 4];
            *(float4*)(bb)     = *(float4*)&Bs[kk][tx * 8];
            *(float4*)(bb + 4) = *(float4*)&Bs[kk][tx * 8 + 4];
            #pragma unroll
            for (int i = 0; i < 8; i++)
                #pragma unroll
                for (int j = 0; j < 8; j++)
                    acc[i][j] += a[i] * bb[j];
        }
        __syncthreads();
    }

    #pragma unroll
    for (int i = 0; i < 8; i++) {
        int c = c0 + ty * 8 + i;
        #pragma unroll
        for (int j4 = 0; j4 < 8; j4 += 4) {
            int q = q0 + tx * 8 + j4;
            if (q < HW) {
                float4 v = make_float4(acc[i][j4], acc[i][j4 + 1],
                                       acc[i][j4 + 2], acc[i][j4 + 3]);
                *(float4*)&Ob[(size_t)c * HW + q] = v;
            }
        }
    }
}

// ---------------- 5) fq = l2norm(f_q) + 0.5 * l2norm(att_fq) -----------------
__global__ void combine_kernel(const float* __restrict__ f_q,
                               float* __restrict__ out_fq) {
    int idx = blockIdx.x * blockDim.x + threadIdx.x;
    if (idx >= NB * HW) return;
    int b = idx / HW, p = idx % HW;
    const float* qb = f_q + (size_t)b * CQ * HW + p;
    const float* ab = g_att + (size_t)b * CQ * HW + p;
    float sq = 0.f, sa = 0.f;
    #pragma unroll 8
    for (int c = 0; c < CQ; c++) {
        float x = qb[(size_t)c * HW]; sq += x * x;
        float y = ab[(size_t)c * HW]; sa += y * y;
    }
    float iq = 1.f / fmaxf(sqrtf(sq), EPS);
    float ia = ATT_WT / fmaxf(sqrtf(sa), EPS);
    float* ob = out_fq + (size_t)b * CQ * HW + p;
    #pragma unroll 8
    for (int c = 0; c < CQ; c++)
        ob[(size_t)c * HW] = qb[(size_t)c * HW] * iq + ab[(size_t)c * HW] * ia;
}

// ---------------- 6) copy att_fq scratch into second output slot -------------
__global__ void copy_att_kernel(float* __restrict__ dst) {
    int i = blockIdx.x * blockDim.x + threadIdx.x;
    int n4 = SZQ / 4;
    if (i < n4)
        ((float4*)dst)[i] = ((const float4*)g_att)[i];
}

// ---------------- launch -----------------------------------------------------
extern "C" void kernel_launch(void* const* d_in, const int* in_sizes, int n_in,
                              void* d_out, int out_size) {
    const float *fq3 = 0, *fs3 = 0, *fq4 = 0, *fs4 = 0, *f_q = 0, *f_s = 0;
    for (int i = 0; i < n_in; i++) {
        const float* p = (const float*)d_in[i];
        int sz = in_sizes[i];
        if (sz == SZ3)      { if (!fq3) fq3 = p; else fs3 = p; }
        else if (sz == SZ4) { if (!fq4) fq4 = p; else fs4 = p; }
        else if (sz == SZQ) { if (!f_q) f_q = p; else f_s = p; }
    }
    float* out = (float*)d_out;

    static int smem_set = 0;
    if (!smem_set) {
        cudaFuncSetAttribute(gemm_corr_mma, cudaFuncAttributeMaxDynamicSharedMemorySize, GEMM_SMEM);
        smem_set = 1;
    }

    norms_kernel<<<114, 256>>>(fq4, C4, 0);
    norms_kernel<<<114, 256>>>(fs4, C4, 1);
    norms_kernel<<<114, 256>>>(fq3, C3, 2);
    norms_kernel<<<114, 256>>>(fs3, C3, 3);

    transpose_kernel<<<dim3(113, C4 / 32, NB), dim3(32, 8)>>>(fq4, C4, 0,  0, 0);
    transpose_kernel<<<dim3(113, C4 / 32, NB), dim3(32, 8)>>>(fs4, C4, 0,  1, 1);
    transpose_kernel<<<dim3(113, C3 / 32, NB), dim3(32, 8)>>>(fq3, C3, C4, 0, 2);
    transpose_kernel<<<dim3(113, C3 / 32, NB), dim3(32, 8)>>>(fs3, C3, C4, 1, 3);

    gemm_corr_mma<<<dim3(29, 29, NB), 256, GEMM_SMEM>>>();

    softmax_kernel<<<NB * HW, 256>>>();

    gemm_att_kernel<<<dim3(29, 2, NB), 256>>>(f_s);

    combine_kernel<<<29, 256>>>(f_q, out);

    if (out_size >= 2 * SZQ) {
        copy_att_kernel<<<(SZQ / 4 + 255) / 256, 256>>>(out + SZQ);
    }
}

// round 8
// speedup vs baseline: 4.9836x; 2.0387x over previous
#include <cuda_runtime.h>
#include <cuda_fp16.h>
#include <cstdint>
#include <math.h>

#define HW     3600
#define NB     2
#define CK     3072      // 2048 + 1024 stacked channels
#define C4     2048
#define C3     1024
#define CQ     256
#define KP     3648      // HW padded to 57*64 for attn GEMM K dim
#define TEMP   20.0f
#define ATT_WT 0.5f
#define EPS    1e-12f

#define SZ3    (NB * C3 * HW)
#define SZ4    (NB * C4 * HW)
#define SZQ    (NB * CQ * HW)

// ---------------- scratch ----------------------------------------------------
__device__ __half g_Ah[(size_t)NB * HW * CK];     // norm q feats half K-major [b][m][k]
__device__ __half g_Bh[(size_t)NB * HW * CK];     // norm s feats half K-major [b][n][k]
__device__ __half g_attnH[(size_t)NB * HW * KP];  // softmaxed attn half      [b][q][s pad]
__device__ __half g_Vh[(size_t)NB * CQ * KP];     // f_s half                 [b][c][s pad]
__device__ float  g_corr[(size_t)NB * HW * HW];   // raw corr logits          [b][q][s]
__device__ float  g_att[(size_t)NB * CQ * HW];    // att_fq fp32              [b][c][q]
__device__ float  g_nrm[16 * NB * HW];            // partial sumsq [sel4][quarter4][b][p]

__device__ __forceinline__ uint32_t smem_u32(const void* p) {
    uint32_t a;
    asm("{ .reg .u64 t; cvta.to.shared.u64 t, %1; cvt.u32.u64 %0, t; }" : "=r"(a) : "l"(p));
    return a;
}

// ---------------- 1a) partial sum-of-squares per pixel (channel quarters) ----
__global__ void norms4_kernel(const float* __restrict__ in, int Cf, int sel) {
    int b   = blockIdx.x / 57;
    int p0  = (blockIdx.x % 57) * 64;
    int cq  = blockIdx.y;                 // channel quarter 0..3
    int Cq  = Cf >> 2;
    int tid = threadIdx.x;
    int cg  = tid >> 6;
    int pl  = tid & 63;
    int p   = p0 + pl;
    bool valid = (p < HW);

    const float* base = in + ((size_t)b * Cf + (size_t)cq * Cq) * HW + p;
    float ss = 0.f;
    if (valid) {
        #pragma unroll 8
        for (int c = cg; c < Cq; c += 4) {
            float v = base[(size_t)c * HW];
            ss += v * v;
        }
    }
    __shared__ float part[4][64];
    part[cg][pl] = ss;
    __syncthreads();
    if (tid < 64 && p0 + tid < HW) {
        float t = part[0][tid] + part[1][tid] + part[2][tid] + part[3][tid];
        g_nrm[(((size_t)sel * 4 + cq) * NB + b) * HW + p0 + tid] = t;
    }
}

// ---------------- 1b) scale + transpose + half into K-major ------------------
__global__ void transpose_kernel(const float* __restrict__ in, int Cf, int coff,
                                 int sel /*0=A 1=B*/, int nsel) {
    __shared__ float t[32][33];
    int b  = blockIdx.z;
    int c0 = blockIdx.y * 32;
    int p0 = blockIdx.x * 32;
    int tx = threadIdx.x, ty = threadIdx.y;   // 32 x 8

    const float* X = in + (size_t)b * Cf * HW;
    __half* T = (sel ? g_Bh : g_Ah) + (size_t)b * HW * CK;

    #pragma unroll
    for (int j = 0; j < 4; j++) {
        int c = c0 + ty + 8 * j;
        int p = p0 + tx;
        t[ty + 8 * j][tx] = (p < HW) ? X[(size_t)c * HW + p] : 0.f;
    }
    __syncthreads();
    #pragma unroll
    for (int j = 0; j < 4; j++) {
        int p = p0 + ty + 8 * j;
        if (p < HW) {
            size_t nb = ((size_t)nsel * 4 * NB + b) * HW + p;
            float s = g_nrm[nb] + g_nrm[nb + (size_t)NB * HW]
                    + g_nrm[nb + (size_t)2 * NB * HW] + g_nrm[nb + (size_t)3 * NB * HW];
            float inv = 1.f / fmaxf(sqrtf(s), EPS);
            T[(size_t)p * CK + coff + c0 + tx] = __float2half_rn(t[tx][ty + 8 * j] * inv);
        }
    }
}

// ---------------- 2) generic fp16 GEMM: C[m][n] = sum_k A[m][k]*B[n][k] ------
// CTA 128x128, k-chunk 64 halves, padded smem rows (72 halves = 144 B),
// scalar u32 fragment loads (R5-proven scheme), mma.m16n8k16 f16 -> f32.
#define SROW_H  72
#define ROW_B   144
#define STG_B   (256 * ROW_B)              // A(128 rows)+B(128 rows) = 36864 B
#define GEMM_SMEM (3 * STG_B)              // 110592 B

__device__ __forceinline__ void mma_f16(float* d, const uint32_t* a, const uint32_t* b) {
    asm volatile(
        "mma.sync.aligned.m16n8k16.row.col.f32.f16.f16.f32 "
        "{%0,%1,%2,%3}, {%4,%5,%6,%7}, {%8,%9}, {%0,%1,%2,%3};"
        : "+f"(d[0]), "+f"(d[1]), "+f"(d[2]), "+f"(d[3])
        : "r"(a[0]), "r"(a[1]), "r"(a[2]), "r"(a[3]), "r"(b[0]), "r"(b[1]));
}

__global__ __launch_bounds__(256, 1)
void gemm_h(const __half* __restrict__ Aall, const __half* __restrict__ Ball,
            float* __restrict__ Call, int ldk, int nIter, int Mg, int Ng,
            size_t strideA, size_t strideB, size_t strideC) {
    extern __shared__ __align__(16) char smh[];
    uint32_t sbase = smem_u32(smh);
    int tid = threadIdx.x;
    int wid = tid >> 5, lane = tid & 31;
    int grp = lane >> 2, tig = lane & 3;
    int wm = (wid & 3) * 32;
    int wn = (wid >> 2) * 64;
    int b  = blockIdx.z;
    int m0 = blockIdx.y * 128;
    int n0 = blockIdx.x * 128;
    const __half* A = Aall + (size_t)b * strideA;
    const __half* B = Ball + (size_t)b * strideB;
    float* Cb = Call + (size_t)b * strideC;

    float acc[2][8][4];
    #pragma unroll
    for (int mi = 0; mi < 2; mi++)
        #pragma unroll
        for (int ni = 0; ni < 8; ni++)
            #pragma unroll
            for (int j = 0; j < 4; j++) acc[mi][ni][j] = 0.f;

    auto load_tile = [&](int iter, int s) {
        int k0 = iter * 64;                   // halves
        uint32_t stA = sbase + s * STG_B;
        #pragma unroll
        for (int j = 0; j < 4; j++) {         // A: 128 rows x 8 chunks
            int f = tid + j * 256;
            int row = f >> 3, q = f & 7;
            uint32_t nb = (m0 + row < Mg) ? 16u : 0u;
            const __half* gp = A + (size_t)(nb ? m0 + row : 0) * ldk + k0 + q * 8;
            uint32_t sa = stA + row * ROW_B + q * 16;
            asm volatile("cp.async.cg.shared.global [%0], [%1], 16, %2;"
                         :: "r"(sa), "l"(gp), "r"(nb) : "memory");
        }
        #pragma unroll
        for (int j = 0; j < 4; j++) {         // B: 128 rows x 8 chunks
            int f = tid + j * 256;
            int row = f >> 3, q = f & 7;
            uint32_t nb = (n0 + row < Ng) ? 16u : 0u;
            const __half* gp = B + (size_t)(nb ? n0 + row : 0) * ldk + k0 + q * 8;
            uint32_t sa = stA + 128 * ROW_B + row * ROW_B + q * 16;
            asm volatile("cp.async.cg.shared.global [%0], [%1], 16, %2;"
                         :: "r"(sa), "l"(gp), "r"(nb) : "memory");
        }
        asm volatile("cp.async.commit_group;" ::: "memory");
    };

    load_tile(0, 0);
    load_tile(1, 1);

    for (int i = 0; i < nIter; i++) {
        int s = i % 3;
        asm volatile("cp.async.wait_group 1;" ::: "memory");
        __syncthreads();
        if (i + 2 < nIter) load_tile(i + 2, (i + 2) % 3);

        const __half* as = (const __half*)(smh + (size_t)s * STG_B);
        const __half* bs = as + 128 * SROW_H;
        #pragma unroll
        for (int ks = 0; ks < 4; ks++) {
            int kk = ks * 16;
            uint32_t af[2][4];
            #pragma unroll
            for (int mi = 0; mi < 2; mi++) {
                int r = wm + mi * 16 + grp;
                af[mi][0] = *(const uint32_t*)&as[r * SROW_H + kk + 2 * tig];
                af[mi][1] = *(const uint32_t*)&as[(r + 8) * SROW_H + kk + 2 * tig];
                af[mi][2] = *(const uint32_t*)&as[r * SROW_H + kk + 8 + 2 * tig];
                af[mi][3] = *(const uint32_t*)&as[(r + 8) * SROW_H + kk + 8 + 2 * tig];
            }
            uint32_t bf[8][2];
            #pragma unroll
            for (int ni = 0; ni < 8; ni++) {
                int r = wn + ni * 8 + grp;
                bf[ni][0] = *(const uint32_t*)&bs[r * SROW_H + kk + 2 * tig];
                bf[ni][1] = *(const uint32_t*)&bs[r * SROW_H + kk + 8 + 2 * tig];
            }
            #pragma unroll
            for (int mi = 0; mi < 2; mi++)
                #pragma unroll
                for (int ni = 0; ni < 8; ni++)
                    mma_f16(acc[mi][ni], af[mi], bf[ni]);
        }
    }

    #pragma unroll
    for (int mi = 0; mi < 2; mi++) {
        int mrow = m0 + wm + mi * 16 + grp;
        #pragma unroll
        for (int ni = 0; ni < 8; ni++) {
            int n = n0 + wn + ni * 8 + 2 * tig;
            if (n < Ng) {
                if (mrow < Mg)
                    *(float2*)&Cb[(size_t)mrow * HW + n] =
                        make_float2(acc[mi][ni][0], acc[mi][ni][1]);
                if (mrow + 8 < Mg)
                    *(float2*)&Cb[(size_t)(mrow + 8) * HW + n] =
                        make_float2(acc[mi][ni][2], acc[mi][ni][3]);
            }
        }
    }
}

// ---------------- 3) row softmax (x10: 0.5 mean * 20 temp), write half -------
__device__ __forceinline__ float warpRedMax(float v) {
    #pragma unroll
    for (int o = 16; o; o >>= 1) v = fmaxf(v, __shfl_xor_sync(0xffffffffu, v, o));
    return v;
}
__device__ __forceinline__ float warpRedSum(float v) {
    #pragma unroll
    for (int o = 16; o; o >>= 1) v += __shfl_xor_sync(0xffffffffu, v, o);
    return v;
}

__global__ void softmax_kernel() {
    int row = blockIdx.x;                          // 0 .. NB*HW-1
    const float* base = g_corr + (size_t)row * HW;
    __half* outp = g_attnH + (size_t)row * KP;
    int tid = threadIdx.x;
    __shared__ float red[8];

    float v[15];
    float mx = -1e30f;
    #pragma unroll
    for (int i = 0; i < 15; i++) {
        int s = tid + i * 256;
        v[i] = (s < HW) ? base[s] * 10.0f : -1e30f;
        mx = fmaxf(mx, v[i]);
    }
    mx = warpRedMax(mx);
    if ((tid & 31) == 0) red[tid >> 5] = mx;
    __syncthreads();
    if (tid < 32) {
        float t = (tid < 8) ? red[tid] : -1e30f;
        t = warpRedMax(t);
        if (tid == 0) red[0] = t;
    }
    __syncthreads();
    mx = red[0];
    __syncthreads();

    float sum = 0.f;
    #pragma unroll
    for (int i = 0; i < 15; i++) {
        int s = tid + i * 256;
        float e = (s < HW) ? expf(v[i] - mx) : 0.f;
        v[i] = e;
        sum += e;
    }
    sum = warpRedSum(sum);
    if ((tid & 31) == 0) red[tid >> 5] = sum;
    __syncthreads();
    if (tid < 32) {
        float t = (tid < 8) ? red[tid] : 0.f;
        t = warpRedSum(t);
        if (tid == 0) red[0] = t;
    }
    __syncthreads();
    float r = 1.f / red[0];

    #pragma unroll
    for (int i = 0; i < 15; i++) {
        int s = tid + i * 256;
        if (s < HW) outp[s] = __float2half_rn(v[i] * r);
    }
    if (tid < KP - HW) outp[HW + tid] = __float2half_rn(0.f);
}

// ---------------- 4) f_s -> half, K-padded ------------------------------------
__global__ void vprep_kernel(const float* __restrict__ V) {
    int idx = blockIdx.x * blockDim.x + threadIdx.x;
    if (idx >= NB * CQ * KP) return;
    int s = idx % KP;
    int bc = idx / KP;
    g_Vh[idx] = __float2half_rn(s < HW ? V[(size_t)bc * HW + s] : 0.f);
}

// ---------------- 5) fq = l2norm(f_q) + 0.5 * l2norm(att_fq) -----------------
__global__ void combine_kernel(const float* __restrict__ f_q,
                               float* __restrict__ out_fq) {
    int idx = blockIdx.x * blockDim.x + threadIdx.x;
    if (idx >= NB * HW) return;
    int b = idx / HW, p = idx % HW;
    const float* qb = f_q + (size_t)b * CQ * HW + p;
    const float* ab = g_att + (size_t)b * CQ * HW + p;
    float sq = 0.f, sa = 0.f;
    #pragma unroll 8
    for (int c = 0; c < CQ; c++) {
        float x = qb[(size_t)c * HW]; sq += x * x;
        float y = ab[(size_t)c * HW]; sa += y * y;
    }
    float iq = 1.f / fmaxf(sqrtf(sq), EPS);
    float ia = ATT_WT / fmaxf(sqrtf(sa), EPS);
    float* ob = out_fq + (size_t)b * CQ * HW + p;
    #pragma unroll 8
    for (int c = 0; c < CQ; c++)
        ob[(size_t)c * HW] = qb[(size_t)c * HW] * iq + ab[(size_t)c * HW] * ia;
}

// ---------------- 6) copy att_fq into second output slot ---------------------
__global__ void copy_att_kernel(float* __restrict__ dst) {
    int i = blockIdx.x * blockDim.x + threadIdx.x;
    if (i < SZQ / 4)
        ((float4*)dst)[i] = ((const float4*)g_att)[i];
}

// ---------------- launch ------------------------------------------------------
extern "C" void kernel_launch(void* const* d_in, const int* in_sizes, int n_in,
                              void* d_out, int out_size) {
    const float *fq3 = 0, *fs3 = 0, *fq4 = 0, *fs4 = 0, *f_q = 0, *f_s = 0;
    for (int i = 0; i < n_in; i++) {
        const float* p = (const float*)d_in[i];
        int sz = in_sizes[i];
        if (sz == SZ3)      { if (!fq3) fq3 = p; else fs3 = p; }
        else if (sz == SZ4) { if (!fq4) fq4 = p; else fs4 = p; }
        else if (sz == SZQ) { if (!f_q) f_q = p; else f_s = p; }
    }
    float* out = (float*)d_out;

    // Resolve TRUE device addresses of scratch symbols. Passing the symbol name
    // directly as a kernel argument from host code passes the host shadow
    // address (ATS makes it silently readable on GB300 -> zeros). This was the
    // R6/R7 bug.
    void *pAh, *pBh, *pAttnH, *pVh, *pCorr, *pAtt;
    cudaGetSymbolAddress(&pAh, g_Ah);
    cudaGetSymbolAddress(&pBh, g_Bh);
    cudaGetSymbolAddress(&pAttnH, g_attnH);
    cudaGetSymbolAddress(&pVh, g_Vh);
    cudaGetSymbolAddress(&pCorr, g_corr);
    cudaGetSymbolAddress(&pAtt, g_att);

    cudaFuncSetAttribute(gemm_h, cudaFuncAttributeMaxDynamicSharedMemorySize, GEMM_SMEM);

    norms4_kernel<<<dim3(114, 4), 256>>>(fq4, C4, 0);
    norms4_kernel<<<dim3(114, 4), 256>>>(fs4, C4, 1);
    norms4_kernel<<<dim3(114, 4), 256>>>(fq3, C3, 2);
    norms4_kernel<<<dim3(114, 4), 256>>>(fs3, C3, 3);

    transpose_kernel<<<dim3(113, C4 / 32, NB), dim3(32, 8)>>>(fq4, C4, 0,  0, 0);
    transpose_kernel<<<dim3(113, C4 / 32, NB), dim3(32, 8)>>>(fs4, C4, 0,  1, 1);
    transpose_kernel<<<dim3(113, C3 / 32, NB), dim3(32, 8)>>>(fq3, C3, C4, 0, 2);
    transpose_kernel<<<dim3(113, C3 / 32, NB), dim3(32, 8)>>>(fs3, C3, C4, 1, 3);

    vprep_kernel<<<(NB * CQ * KP + 255) / 256, 256>>>(f_s);

    // corr: A=g_Ah[m=q][k], B=g_Bh[n=s][k], C=g_corr[q][s]
    gemm_h<<<dim3(29, 29, NB), 256, GEMM_SMEM>>>(
        (const __half*)pAh, (const __half*)pBh, (float*)pCorr,
        CK, CK / 64, HW, HW,
        (size_t)HW * CK, (size_t)HW * CK, (size_t)HW * HW);

    softmax_kernel<<<NB * HW, 256>>>();

    // attn: A=g_Vh[m=c][s], B=g_attnH[n=q][s], C=g_att[c][q]
    gemm_h<<<dim3(29, 2, NB), 256, GEMM_SMEM>>>(
        (const __half*)pVh, (const __half*)pAttnH, (float*)pAtt,
        KP, KP / 64, CQ, HW,
        (size_t)CQ * KP, (size_t)HW * KP, (size_t)CQ * HW);

    combine_kernel<<<29, 256>>>(f_q, out);

    if (out_size >= 2 * SZQ) {
        copy_att_kernel<<<(SZQ / 4 + 255) / 256, 256>>>(out + SZQ);
    }
}

// round 9
// speedup vs baseline: 5.3962x; 1.0828x over previous
#include <cuda_runtime.h>
#include <cuda_fp16.h>
#include <cstdint>
#include <math.h>

#define HW     3600
#define NB     2
#define CK     3072      // 2048 + 1024 stacked channels
#define C4     2048
#define C3     1024
#define CQ     256
#define KP     3648      // HW padded for attn GEMM K dim
#define TEMP   20.0f
#define ATT_WT 0.5f
#define EPS    1e-12f

#define SZ3    (NB * C3 * HW)
#define SZ4    (NB * C4 * HW)
#define SZQ    (NB * CQ * HW)

// ---------------- scratch ----------------------------------------------------
__device__ __half g_Ah[(size_t)NB * HW * CK];     // norm q feats half K-major [b][m][k]
__device__ __half g_Bh[(size_t)NB * HW * CK];     // norm s feats half K-major [b][n][k]
__device__ __half g_attnH[(size_t)NB * HW * KP];  // softmaxed attn half      [b][q][s pad]
__device__ __half g_Vh[(size_t)NB * CQ * KP];     // f_s half                 [b][c][s pad]
__device__ float  g_corr[(size_t)NB * HW * HW];   // corr logits (x10)        [b][q][s]
__device__ float  g_att[(size_t)NB * CQ * HW];    // att_fq fp32              [b][c][q]
__device__ float  g_nrm[16 * NB * HW];            // partial sumsq [sel4][quarter4][b][p]

__device__ __forceinline__ uint32_t smem_u32(const void* p) {
    uint32_t a;
    asm("{ .reg .u64 t; cvta.to.shared.u64 t, %1; cvt.u32.u64 %0, t; }" : "=r"(a) : "l"(p));
    return a;
}

// ---------------- 1a) partial sum-of-squares (grid.z = channel quarter) ------
__global__ void norms4_kernel(const float* __restrict__ inA,
                              const float* __restrict__ inB,
                              int Cf, int selbase) {
    int which = blockIdx.y;               // 0 = q tensor, 1 = s tensor
    const float* in = which ? inB : inA;
    int sel = selbase + which;
    int b   = blockIdx.x / 57;
    int p0  = (blockIdx.x % 57) * 64;
    int cq  = blockIdx.z;                 // channel quarter 0..3
    int Cq  = Cf >> 2;
    int tid = threadIdx.x;
    int cg  = tid >> 6;
    int pl  = tid & 63;
    int p   = p0 + pl;
    bool valid = (p < HW);

    const float* base = in + ((size_t)b * Cf + (size_t)cq * Cq) * HW + p;
    float ss = 0.f;
    if (valid) {
        #pragma unroll 8
        for (int c = cg; c < Cq; c += 4) {
            float v = base[(size_t)c * HW];
            ss += v * v;
        }
    }
    __shared__ float part[4][64];
    part[cg][pl] = ss;
    __syncthreads();
    if (tid < 64 && p0 + tid < HW) {
        float t = part[0][tid] + part[1][tid] + part[2][tid] + part[3][tid];
        g_nrm[(((size_t)sel * 4 + cq) * NB + b) * HW + p0 + tid] = t;
    }
}

// ---------------- 1b) scale + transpose + half into K-major ------------------
__global__ void transpose_kernel(const float* __restrict__ in, int Cf, int coff,
                                 int sel /*0=A 1=B*/, int nsel) {
    __shared__ float t[32][33];
    int b  = blockIdx.z;
    int c0 = blockIdx.y * 32;
    int p0 = blockIdx.x * 32;
    int tx = threadIdx.x, ty = threadIdx.y;   // 32 x 8

    const float* X = in + (size_t)b * Cf * HW;
    __half* T = (sel ? g_Bh : g_Ah) + (size_t)b * HW * CK;

    #pragma unroll
    for (int j = 0; j < 4; j++) {
        int c = c0 + ty + 8 * j;
        int p = p0 + tx;
        t[ty + 8 * j][tx] = (p < HW) ? X[(size_t)c * HW + p] : 0.f;
    }
    __syncthreads();
    #pragma unroll
    for (int j = 0; j < 4; j++) {
        int p = p0 + ty + 8 * j;
        if (p < HW) {
            size_t nb = ((size_t)nsel * 4 * NB + b) * HW + p;
            float s = g_nrm[nb] + g_nrm[nb + (size_t)NB * HW]
                    + g_nrm[nb + (size_t)2 * NB * HW] + g_nrm[nb + (size_t)3 * NB * HW];
            float inv = 1.f / fmaxf(sqrtf(s), EPS);
            T[(size_t)p * CK + coff + c0 + tx] = __float2half_rn(t[tx][ty + 8 * j] * inv);
        }
    }
}

// ---------------- 2) generic fp16 GEMM: C[m][n] = cs * sum_k A[m][k]*B[n][k] -
// CTA 128x128, k-chunk 64 halves, padded smem rows (72 halves = 144 B),
// scalar u32 fragment loads, mma.m16n8k16 f16->f32, 2-stage cp.async,
// 2 CTAs/SM for cross-CTA latency hiding.
#define SROW_H  72
#define ROW_B   144
#define STG_B   (256 * ROW_B)              // A(128 rows)+B(128 rows) = 36864 B
#define GEMM_SMEM (2 * STG_B)              // 73728 B -> 2 CTAs/SM

__device__ __forceinline__ void mma_f16(float* d, const uint32_t* a, const uint32_t* b) {
    asm volatile(
        "mma.sync.aligned.m16n8k16.row.col.f32.f16.f16.f32 "
        "{%0,%1,%2,%3}, {%4,%5,%6,%7}, {%8,%9}, {%0,%1,%2,%3};"
        : "+f"(d[0]), "+f"(d[1]), "+f"(d[2]), "+f"(d[3])
        : "r"(a[0]), "r"(a[1]), "r"(a[2]), "r"(a[3]), "r"(b[0]), "r"(b[1]));
}

__global__ __launch_bounds__(256, 2)
void gemm_h(const __half* __restrict__ Aall, const __half* __restrict__ Ball,
            float* __restrict__ Call, int ldk, int nIter, int Mg, int Ng,
            size_t strideA, size_t strideB, size_t strideC, float cs) {
    extern __shared__ __align__(16) char smh[];
    uint32_t sbase = smem_u32(smh);
    int tid = threadIdx.x;
    int wid = tid >> 5, lane = tid & 31;
    int grp = lane >> 2, tig = lane & 3;
    int wm = (wid & 3) * 32;
    int wn = (wid >> 2) * 64;
    int b  = blockIdx.z;
    int m0 = blockIdx.y * 128;
    int n0 = blockIdx.x * 128;
    const __half* A = Aall + (size_t)b * strideA;
    const __half* B = Ball + (size_t)b * strideB;
    float* Cb = Call + (size_t)b * strideC;

    float acc[2][8][4];
    #pragma unroll
    for (int mi = 0; mi < 2; mi++)
        #pragma unroll
        for (int ni = 0; ni < 8; ni++)
            #pragma unroll
            for (int j = 0; j < 4; j++) acc[mi][ni][j] = 0.f;

    auto load_tile = [&](int iter, int s) {
        int k0 = iter * 64;                   // halves
        uint32_t stA = sbase + s * STG_B;
        #pragma unroll
        for (int j = 0; j < 4; j++) {         // A: 128 rows x 8 chunks
            int f = tid + j * 256;
            int row = f >> 3, q = f & 7;
            uint32_t nb = (m0 + row < Mg) ? 16u : 0u;
            const __half* gp = A + (size_t)(nb ? m0 + row : 0) * ldk + k0 + q * 8;
            uint32_t sa = stA + row * ROW_B + q * 16;
            asm volatile("cp.async.cg.shared.global [%0], [%1], 16, %2;"
                         :: "r"(sa), "l"(gp), "r"(nb) : "memory");
        }
        #pragma unroll
        for (int j = 0; j < 4; j++) {         // B: 128 rows x 8 chunks
            int f = tid + j * 256;
            int row = f >> 3, q = f & 7;
            uint32_t nb = (n0 + row < Ng) ? 16u : 0u;
            const __half* gp = B + (size_t)(nb ? n0 + row : 0) * ldk + k0 + q * 8;
            uint32_t sa = stA + 128 * ROW_B + row * ROW_B + q * 16;
            asm volatile("cp.async.cg.shared.global [%0], [%1], 16, %2;"
                         :: "r"(sa), "l"(gp), "r"(nb) : "memory");
        }
        asm volatile("cp.async.commit_group;" ::: "memory");
    };

    load_tile(0, 0);
    load_tile(1, 1);

    for (int i = 0; i < nIter; i++) {
        int s = i & 1;
        asm volatile("cp.async.wait_group 1;" ::: "memory");
        __syncthreads();

        const __half* as = (const __half*)(smh + (size_t)s * STG_B);
        const __half* bs = as + 128 * SROW_H;
        #pragma unroll
        for (int ks = 0; ks < 4; ks++) {
            int kk = ks * 16;
            uint32_t af[2][4];
            #pragma unroll
            for (int mi = 0; mi < 2; mi++) {
                int r = wm + mi * 16 + grp;
                af[mi][0] = *(const uint32_t*)&as[r * SROW_H + kk + 2 * tig];
                af[mi][1] = *(const uint32_t*)&as[(r + 8) * SROW_H + kk + 2 * tig];
                af[mi][2] = *(const uint32_t*)&as[r * SROW_H + kk + 8 + 2 * tig];
                af[mi][3] = *(const uint32_t*)&as[(r + 8) * SROW_H + kk + 8 + 2 * tig];
            }
            uint32_t bf[8][2];
            #pragma unroll
            for (int ni = 0; ni < 8; ni++) {
                int r = wn + ni * 8 + grp;
                bf[ni][0] = *(const uint32_t*)&bs[r * SROW_H + kk + 2 * tig];
                bf[ni][1] = *(const uint32_t*)&bs[r * SROW_H + kk + 8 + 2 * tig];
            }
            #pragma unroll
            for (int mi = 0; mi < 2; mi++)
                #pragma unroll
                for (int ni = 0; ni < 8; ni++)
                    mma_f16(acc[mi][ni], af[mi], bf[ni]);
        }
        __syncthreads();
        if (i + 2 < nIter) load_tile(i + 2, s);
    }

    #pragma unroll
    for (int mi = 0; mi < 2; mi++) {
        int mrow = m0 + wm + mi * 16 + grp;
        #pragma unroll
        for (int ni = 0; ni < 8; ni++) {
            int n = n0 + wn + ni * 8 + 2 * tig;
            if (n < Ng) {
                if (mrow < Mg)
                    *(float2*)&Cb[(size_t)mrow * HW + n] =
                        make_float2(cs * acc[mi][ni][0], cs * acc[mi][ni][1]);
                if (mrow + 8 < Mg)
                    *(float2*)&Cb[(size_t)(mrow + 8) * HW + n] =
                        make_float2(cs * acc[mi][ni][2], cs * acc[mi][ni][3]);
            }
        }
    }
}

// ---------------- 3) row softmax (logits pre-scaled x10), write half ---------
__device__ __forceinline__ float warpRedMax(float v) {
    #pragma unroll
    for (int o = 16; o; o >>= 1) v = fmaxf(v, __shfl_xor_sync(0xffffffffu, v, o));
    return v;
}
__device__ __forceinline__ float warpRedSum(float v) {
    #pragma unroll
    for (int o = 16; o; o >>= 1) v += __shfl_xor_sync(0xffffffffu, v, o);
    return v;
}

__global__ void softmax_kernel() {
    int row = blockIdx.x;                          // 0 .. NB*HW-1
    const float* base = g_corr + (size_t)row * HW;
    __half* outp = g_attnH + (size_t)row * KP;
    int tid = threadIdx.x;
    __shared__ float red[8];

    float v[15];
    float mx = -1e30f;
    #pragma unroll
    for (int i = 0; i < 15; i++) {
        int s = tid + i * 256;
        v[i] = (s < HW) ? base[s] : -1e30f;
        mx = fmaxf(mx, v[i]);
    }
    mx = warpRedMax(mx);
    if ((tid & 31) == 0) red[tid >> 5] = mx;
    __syncthreads();
    if (tid < 32) {
        float t = (tid < 8) ? red[tid] : -1e30f;
        t = warpRedMax(t);
        if (tid == 0) red[0] = t;
    }
    __syncthreads();
    mx = red[0];
    __syncthreads();

    float sum = 0.f;
    #pragma unroll
    for (int i = 0; i < 15; i++) {
        int s = tid + i * 256;
        float e = (s < HW) ? expf(v[i] - mx) : 0.f;
        v[i] = e;
        sum += e;
    }
    sum = warpRedSum(sum);
    if ((tid & 31) == 0) red[tid >> 5] = sum;
    __syncthreads();
    if (tid < 32) {
        float t = (tid < 8) ? red[tid] : 0.f;
        t = warpRedSum(t);
        if (tid == 0) red[0] = t;
    }
    __syncthreads();
    float r = 1.f / red[0];

    #pragma unroll
    for (int i = 0; i < 15; i++) {
        int s = tid + i * 256;
        if (s < HW) outp[s] = __float2half_rn(v[i] * r);
    }
    if (tid < KP - HW) outp[HW + tid] = __float2half_rn(0.f);
}

// ---------------- 4) f_s -> half, K-padded ------------------------------------
__global__ void vprep_kernel(const float* __restrict__ V) {
    int idx = blockIdx.x * blockDim.x + threadIdx.x;
    if (idx >= NB * CQ * KP) return;
    int s = idx % KP;
    int bc = idx / KP;
    g_Vh[idx] = __float2half_rn(s < HW ? V[(size_t)bc * HW + s] : 0.f);
}

// ---------------- 5) fq = l2norm(f_q) + 0.5 * l2norm(att_fq) -----------------
__global__ void combine_kernel(const float* __restrict__ f_q,
                               float* __restrict__ out_fq) {
    int idx = blockIdx.x * blockDim.x + threadIdx.x;
    if (idx >= NB * HW) return;
    int b = idx / HW, p = idx % HW;
    const float* qb = f_q + (size_t)b * CQ * HW + p;
    const float* ab = g_att + (size_t)b * CQ * HW + p;
    float sq = 0.f, sa = 0.f;
    #pragma unroll 8
    for (int c = 0; c < CQ; c++) {
        float x = qb[(size_t)c * HW]; sq += x * x;
        float y = ab[(size_t)c * HW]; sa += y * y;
    }
    float iq = 1.f / fmaxf(sqrtf(sq), EPS);
    float ia = ATT_WT / fmaxf(sqrtf(sa), EPS);
    float* ob = out_fq + (size_t)b * CQ * HW + p;
    #pragma unroll 8
    for (int c = 0; c < CQ; c++)
        ob[(size_t)c * HW] = qb[(size_t)c * HW] * iq + ab[(size_t)c * HW] * ia;
}

// ---------------- 6) copy att_fq into second output slot ---------------------
__global__ void copy_att_kernel(float* __restrict__ dst) {
    int i = blockIdx.x * blockDim.x + threadIdx.x;
    if (i < SZQ / 4)
        ((float4*)dst)[i] = ((const float4*)g_att)[i];
}

// ---------------- launch ------------------------------------------------------
extern "C" void kernel_launch(void* const* d_in, const int* in_sizes, int n_in,
                              void* d_out, int out_size) {
    const float *fq3 = 0, *fs3 = 0, *fq4 = 0, *fs4 = 0, *f_q = 0, *f_s = 0;
    for (int i = 0; i < n_in; i++) {
        const float* p = (const float*)d_in[i];
        int sz = in_sizes[i];
        if (sz == SZ3)      { if (!fq3) fq3 = p; else fs3 = p; }
        else if (sz == SZ4) { if (!fq4) fq4 = p; else fs4 = p; }
        else if (sz == SZQ) { if (!f_q) f_q = p; else f_s = p; }
    }
    float* out = (float*)d_out;

    // Resolve TRUE device addresses of scratch symbols (host shadow symbols are
    // silently ATS-dereferenceable on GB300 -> the R6/R7 zero-data bug).
    void *pAh, *pBh, *pAttnH, *pVh, *pCorr, *pAtt;
    cudaGetSymbolAddress(&pAh, g_Ah);
    cudaGetSymbolAddress(&pBh, g_Bh);
    cudaGetSymbolAddress(&pAttnH, g_attnH);
    cudaGetSymbolAddress(&pVh, g_Vh);
    cudaGetSymbolAddress(&pCorr, g_corr);
    cudaGetSymbolAddress(&pAtt, g_att);

    cudaFuncSetAttribute(gemm_h, cudaFuncAttributeMaxDynamicSharedMemorySize, GEMM_SMEM);

    norms4_kernel<<<dim3(114, 2, 4), 256>>>(fq4, fs4, C4, 0);
    norms4_kernel<<<dim3(114, 2, 4), 256>>>(fq3, fs3, C3, 2);

    transpose_kernel<<<dim3(113, C4 / 32, NB), dim3(32, 8)>>>(fq4, C4, 0,  0, 0);
    transpose_kernel<<<dim3(113, C4 / 32, NB), dim3(32, 8)>>>(fs4, C4, 0,  1, 1);
    transpose_kernel<<<dim3(113, C3 / 32, NB), dim3(32, 8)>>>(fq3, C3, C4, 0, 2);
    transpose_kernel<<<dim3(113, C3 / 32, NB), dim3(32, 8)>>>(fs3, C3, C4, 1, 3);

    vprep_kernel<<<(NB * CQ * KP + 255) / 256, 256>>>(f_s);

    // corr logits (x10 = 0.5 mean * 20 temp folded into epilogue)
    gemm_h<<<dim3(29, 29, NB), 256, GEMM_SMEM>>>(
        (const __half*)pAh, (const __half*)pBh, (float*)pCorr,
        CK, CK / 64, HW, HW,
        (size_t)HW * CK, (size_t)HW * CK, (size_t)HW * HW, 10.0f);

    softmax_kernel<<<NB * HW, 256>>>();

    // attn: A=g_Vh[m=c][s], B=g_attnH[n=q][s], C=g_att[c][q]
    gemm_h<<<dim3(29, 2, NB), 256, GEMM_SMEM>>>(
        (const __half*)pVh, (const __half*)pAttnH, (float*)pAtt,
        KP, KP / 64, CQ, HW,
        (size_t)CQ * KP, (size_t)HW * KP, (size_t)CQ * HW, 1.0f);

    combine_kernel<<<29, 256>>>(f_q, out);

    if (out_size >= 2 * SZQ) {
        copy_att_kernel<<<(SZQ / 4 + 255) / 256, 256>>>(out + SZQ);
    }
}

// round 10
// speedup vs baseline: 5.6772x; 1.0521x over previous
#include <cuda_runtime.h>
#include <cuda_fp16.h>
#include <cstdint>
#include <math.h>

#define HW     3600
#define NB     2
#define CK     3072      // 2048 + 1024 stacked channels
#define C4     2048
#define C3     1024
#define CQ     256
#define KP     3648      // HW padded for attn GEMM K dim
#define TEMP   20.0f
#define ATT_WT 0.5f
#define EPS    1e-12f

#define SZ3    (NB * C3 * HW)
#define SZ4    (NB * C4 * HW)
#define SZQ    (NB * CQ * HW)

// ---------------- scratch ----------------------------------------------------
__device__ __half g_Ah[(size_t)NB * HW * CK];     // norm q feats half K-major [b][m][k]
__device__ __half g_Bh[(size_t)NB * HW * CK];     // norm s feats half K-major [b][n][k]
__device__ __half g_attnH[(size_t)NB * HW * KP];  // softmaxed attn half      [b][q][s pad]
__device__ __half g_Vh[(size_t)NB * CQ * KP];     // f_s half                 [b][c][s pad]
__device__ float  g_corr[(size_t)NB * HW * HW];   // corr logits (x10)        [b][q][s]
__device__ float  g_attP[(size_t)NB * 2 * CQ * HW]; // split-K partials       [b*2+k][c][q]
__device__ float  g_att[(size_t)NB * CQ * HW];    // att_fq fp32              [b][c][q]
__device__ float  g_nrm[16 * NB * HW];            // partial sumsq [sel4][quarter4][b][p]

__device__ __forceinline__ uint32_t smem_u32(const void* p) {
    uint32_t a;
    asm("{ .reg .u64 t; cvta.to.shared.u64 t, %1; cvt.u32.u64 %0, t; }" : "=r"(a) : "l"(p));
    return a;
}

// ---------------- 1a) partial sum-of-squares (grid.z = channel quarter) ------
__global__ void norms4_kernel(const float* __restrict__ inA,
                              const float* __restrict__ inB,
                              int Cf, int selbase) {
    int which = blockIdx.y;               // 0 = q tensor, 1 = s tensor
    const float* in = which ? inB : inA;
    int sel = selbase + which;
    int b   = blockIdx.x / 57;
    int p0  = (blockIdx.x % 57) * 64;
    int cq  = blockIdx.z;                 // channel quarter 0..3
    int Cq  = Cf >> 2;
    int tid = threadIdx.x;
    int cg  = tid >> 6;
    int pl  = tid & 63;
    int p   = p0 + pl;
    bool valid = (p < HW);

    const float* base = in + ((size_t)b * Cf + (size_t)cq * Cq) * HW + p;
    float ss = 0.f;
    if (valid) {
        #pragma unroll 8
        for (int c = cg; c < Cq; c += 4) {
            float v = base[(size_t)c * HW];
            ss += v * v;
        }
    }
    __shared__ float part[4][64];
    part[cg][pl] = ss;
    __syncthreads();
    if (tid < 64 && p0 + tid < HW) {
        float t = part[0][tid] + part[1][tid] + part[2][tid] + part[3][tid];
        g_nrm[(((size_t)sel * 4 + cq) * NB + b) * HW + p0 + tid] = t;
    }
}

// ---------------- 1b) scale + transpose + half into K-major ------------------
// tile: 64 channels x 32 pixels per block; half smem, conflict-free both ways;
// 128B coalesced half2 stores.
__global__ void transpose_kernel(const float* __restrict__ in, int Cf, int coff,
                                 int sel /*0=A 1=B*/, int nsel) {
    __shared__ __half sh[32][66];
    int b  = blockIdx.z;
    int c0 = blockIdx.y * 64;
    int p0 = blockIdx.x * 32;
    int tid = threadIdx.x;
    int tx = tid & 31, ty = tid >> 5;       // ty 0..7

    int p = p0 + tx;
    bool pv = (p < HW);
    float inv = 0.f;
    if (pv) {
        size_t nb = ((size_t)nsel * 4 * NB + b) * HW + p;
        float s = g_nrm[nb] + g_nrm[nb + (size_t)NB * HW]
                + g_nrm[nb + (size_t)2 * NB * HW] + g_nrm[nb + (size_t)3 * NB * HW];
        inv = 1.f / fmaxf(sqrtf(s), EPS);
    }
    const float* X = in + ((size_t)b * Cf + c0) * HW + p;
    #pragma unroll
    for (int j = 0; j < 8; j++) {
        int c = ty * 8 + j;
        float v = pv ? X[(size_t)c * HW] : 0.f;
        sh[tx][c] = __float2half_rn(v * inv);
    }
    __syncthreads();
    __half* T = (sel ? g_Bh : g_Ah) + (size_t)b * HW * CK + coff + c0;
    #pragma unroll
    for (int k = 0; k < 4; k++) {
        int e  = tid + k * 256;
        int pr = e >> 5;                    // 0..31
        int ln = e & 31;                    // half2 index along c
        if (p0 + pr < HW) {
            uint32_t w = *(const uint32_t*)&sh[pr][2 * ln];
            *(uint32_t*)&T[(size_t)(p0 + pr) * CK + 2 * ln] = w;
        }
    }
}

// ---------------- 2) generic fp16 GEMM (optional split-K) --------------------
// C[z][m][n] = cs * sum_{k in split} A[m][k]*B[n][k];  z = b*nSplit + ksp
#define SROW_H  72
#define ROW_B   144
#define STG_B   (256 * ROW_B)              // 36864 B
#define GEMM_SMEM (2 * STG_B)              // 73728 B -> 2 CTAs/SM

__device__ __forceinline__ void mma_f16(float* d, const uint32_t* a, const uint32_t* b) {
    asm volatile(
        "mma.sync.aligned.m16n8k16.row.col.f32.f16.f16.f32 "
        "{%0,%1,%2,%3}, {%4,%5,%6,%7}, {%8,%9}, {%0,%1,%2,%3};"
        : "+f"(d[0]), "+f"(d[1]), "+f"(d[2]), "+f"(d[3])
        : "r"(a[0]), "r"(a[1]), "r"(a[2]), "r"(a[3]), "r"(b[0]), "r"(b[1]));
}

__global__ __launch_bounds__(256, 2)
void gemm_h(const __half* __restrict__ Aall, const __half* __restrict__ Ball,
            float* __restrict__ Call, int ldk, int nIter, int Mg, int Ng,
            size_t strideA, size_t strideB, size_t strideC, float cs, int nSplit) {
    extern __shared__ __align__(16) char smh[];
    uint32_t sbase = smem_u32(smh);
    int tid = threadIdx.x;
    int wid = tid >> 5, lane = tid & 31;
    int grp = lane >> 2, tig = lane & 3;
    int wm = (wid & 3) * 32;
    int wn = (wid >> 2) * 64;
    int z   = blockIdx.z;
    int b   = z / nSplit;
    int ksp = z - b * nSplit;
    int m0 = blockIdx.y * 128;
    int n0 = blockIdx.x * 128;
    const __half* A = Aall + (size_t)b * strideA;
    const __half* B = Ball + (size_t)b * strideB;
    float* Cb = Call + (size_t)z * strideC;

    int per = (nIter + nSplit - 1) / nSplit;
    int i0  = ksp * per;
    int i1  = min(nIter, i0 + per);

    float acc[2][8][4];
    #pragma unroll
    for (int mi = 0; mi < 2; mi++)
        #pragma unroll
        for (int ni = 0; ni < 8; ni++)
            #pragma unroll
            for (int j = 0; j < 4; j++) acc[mi][ni][j] = 0.f;

    auto load_tile = [&](int iter, int s) {
        int k0 = iter * 64;                   // halves
        uint32_t stA = sbase + s * STG_B;
        #pragma unroll
        for (int j = 0; j < 4; j++) {         // A: 128 rows x 8 chunks
            int f = tid + j * 256;
            int row = f >> 3, q = f & 7;
            uint32_t nb = (m0 + row < Mg) ? 16u : 0u;
            const __half* gp = A + (size_t)(nb ? m0 + row : 0) * ldk + k0 + q * 8;
            uint32_t sa = stA + row * ROW_B + q * 16;
            asm volatile("cp.async.cg.shared.global [%0], [%1], 16, %2;"
                         :: "r"(sa), "l"(gp), "r"(nb) : "memory");
        }
        #pragma unroll
        for (int j = 0; j < 4; j++) {         // B: 128 rows x 8 chunks
            int f = tid + j * 256;
            int row = f >> 3, q = f & 7;
            uint32_t nb = (n0 + row < Ng) ? 16u : 0u;
            const __half* gp = B + (size_t)(nb ? n0 + row : 0) * ldk + k0 + q * 8;
            uint32_t sa = stA + 128 * ROW_B + row * ROW_B + q * 16;
            asm volatile("cp.async.cg.shared.global [%0], [%1], 16, %2;"
                         :: "r"(sa), "l"(gp), "r"(nb) : "memory");
        }
        asm volatile("cp.async.commit_group;" ::: "memory");
    };

    load_tile(i0, 0);
    if (i0 + 1 < i1) load_tile(i0 + 1, 1);

    for (int i = i0; i < i1; i++) {
        int s = (i - i0) & 1;
        // last iteration has only 1 pending group: must wait to 0, not 1
        if (i + 1 < i1) { asm volatile("cp.async.wait_group 1;" ::: "memory"); }
        else           { asm volatile("cp.async.wait_group 0;" ::: "memory"); }
        __syncthreads();

        const __half* as = (const __half*)(smh + (size_t)s * STG_B);
        const __half* bs = as + 128 * SROW_H;
        #pragma unroll
        for (int ks = 0; ks < 4; ks++) {
            int kk = ks * 16;
            uint32_t af[2][4];
            #pragma unroll
            for (int mi = 0; mi < 2; mi++) {
                int r = wm + mi * 16 + grp;
                af[mi][0] = *(const uint32_t*)&as[r * SROW_H + kk + 2 * tig];
                af[mi][1] = *(const uint32_t*)&as[(r + 8) * SROW_H + kk + 2 * tig];
                af[mi][2] = *(const uint32_t*)&as[r * SROW_H + kk + 8 + 2 * tig];
                af[mi][3] = *(const uint32_t*)&as[(r + 8) * SROW_H + kk + 8 + 2 * tig];
            }
            uint32_t bf[8][2];
            #pragma unroll
            for (int ni = 0; ni < 8; ni++) {
                int r = wn + ni * 8 + grp;
                bf[ni][0] = *(const uint32_t*)&bs[r * SROW_H + kk + 2 * tig];
                bf[ni][1] = *(const uint32_t*)&bs[r * SROW_H + kk + 8 + 2 * tig];
            }
            #pragma unroll
            for (int mi = 0; mi < 2; mi++)
                #pragma unroll
                for (int ni = 0; ni < 8; ni++)
                    mma_f16(acc[mi][ni], af[mi], bf[ni]);
        }
        __syncthreads();
        if (i + 2 < i1) load_tile(i + 2, s);
    }

    #pragma unroll
    for (int mi = 0; mi < 2; mi++) {
        int mrow = m0 + wm + mi * 16 + grp;
        #pragma unroll
        for (int ni = 0; ni < 8; ni++) {
            int n = n0 + wn + ni * 8 + 2 * tig;
            if (n < Ng) {
                if (mrow < Mg)
                    *(float2*)&Cb[(size_t)mrow * HW + n] =
                        make_float2(cs * acc[mi][ni][0], cs * acc[mi][ni][1]);
                if (mrow + 8 < Mg)
                    *(float2*)&Cb[(size_t)(mrow + 8) * HW + n] =
                        make_float2(cs * acc[mi][ni][2], cs * acc[mi][ni][3]);
            }
        }
    }
}

// ---------------- 2b) split-K reduce: g_att = partial0 + partial1 ------------
__global__ void att_reduce_kernel() {
    int idx = blockIdx.x * blockDim.x + threadIdx.x;
    if (idx >= SZQ / 4) return;
    int i4 = idx * 4;
    int b = i4 / (CQ * HW);
    int r = i4 - b * (CQ * HW);
    const float4* p0 = (const float4*)&g_attP[((size_t)2 * b) * CQ * HW + r];
    const float4* p1 = (const float4*)&g_attP[((size_t)2 * b + 1) * CQ * HW + r];
    float4 a = *p0, c = *p1;
    ((float4*)g_att)[idx] = make_float4(a.x + c.x, a.y + c.y, a.z + c.z, a.w + c.w);
}

// ---------------- 3) row softmax (logits pre-scaled x10), write half ---------
__device__ __forceinline__ float warpRedMax(float v) {
    #pragma unroll
    for (int o = 16; o; o >>= 1) v = fmaxf(v, __shfl_xor_sync(0xffffffffu, v, o));
    return v;
}
__device__ __forceinline__ float warpRedSum(float v) {
    #pragma unroll
    for (int o = 16; o; o >>= 1) v += __shfl_xor_sync(0xffffffffu, v, o);
    return v;
}

__global__ void softmax_kernel() {
    int row = blockIdx.x;                          // 0 .. NB*HW-1
    const float* base = g_corr + (size_t)row * HW;
    __half* outp = g_attnH + (size_t)row * KP;
    int tid = threadIdx.x;
    __shared__ float red[8];

    float v[15];
    float mx = -1e30f;
    #pragma unroll
    for (int i = 0; i < 15; i++) {
        int s = tid + i * 256;
        v[i] = (s < HW) ? base[s] : -1e30f;
        mx = fmaxf(mx, v[i]);
    }
    mx = warpRedMax(mx);
    if ((tid & 31) == 0) red[tid >> 5] = mx;
    __syncthreads();
    if (tid < 32) {
        float t = (tid < 8) ? red[tid] : -1e30f;
        t = warpRedMax(t);
        if (tid == 0) red[0] = t;
    }
    __syncthreads();
    mx = red[0];
    __syncthreads();

    float sum = 0.f;
    #pragma unroll
    for (int i = 0; i < 15; i++) {
        int s = tid + i * 256;
        float e = (s < HW) ? expf(v[i] - mx) : 0.f;
        v[i] = e;
        sum += e;
    }
    sum = warpRedSum(sum);
    if ((tid & 31) == 0) red[tid >> 5] = sum;
    __syncthreads();
    if (tid < 32) {
        float t = (tid < 8) ? red[tid] : 0.f;
        t = warpRedSum(t);
        if (tid == 0) red[0] = t;
    }
    __syncthreads();
    float r = 1.f / red[0];

    #pragma unroll
    for (int i = 0; i < 15; i++) {
        int s = tid + i * 256;
        if (s < HW) outp[s] = __float2half_rn(v[i] * r);
    }
    if (tid < KP - HW) outp[HW + tid] = __float2half_rn(0.f);
}

// ---------------- 4) f_s -> half, K-padded ------------------------------------
__global__ void vprep_kernel(const float* __restrict__ V) {
    int idx = blockIdx.x * blockDim.x + threadIdx.x;
    if (idx >= NB * CQ * KP) return;
    int s = idx % KP;
    int bc = idx / KP;
    g_Vh[idx] = __float2half_rn(s < HW ? V[(size_t)bc * HW + s] : 0.f);
}

// ---------------- 5) fq = l2norm(f_q) + 0.5 * l2norm(att_fq); emit att -------
__global__ void combine_kernel(const float* __restrict__ f_q,
                               float* __restrict__ out_fq,
                               float* __restrict__ out_att, int writeAtt) {
    int idx = blockIdx.x * blockDim.x + threadIdx.x;
    if (idx >= NB * HW) return;
    int b = idx / HW, p = idx % HW;
    const float* qb = f_q + (size_t)b * CQ * HW + p;
    const float* ab = g_att + (size_t)b * CQ * HW + p;
    float sq = 0.f, sa = 0.f;
    #pragma unroll 8
    for (int c = 0; c < CQ; c++) {
        float x = qb[(size_t)c * HW]; sq += x * x;
        float y = ab[(size_t)c * HW]; sa += y * y;
    }
    float iq = 1.f / fmaxf(sqrtf(sq), EPS);
    float ia = ATT_WT / fmaxf(sqrtf(sa), EPS);
    float* ob = out_fq + (size_t)b * CQ * HW + p;
    if (writeAtt) {
        float* oa = out_att + (size_t)b * CQ * HW + p;
        #pragma unroll 4
        for (int c = 0; c < CQ; c++) {
            float y = ab[(size_t)c * HW];
            ob[(size_t)c * HW] = qb[(size_t)c * HW] * iq + y * ia;
            oa[(size_t)c * HW] = y;
        }
    } else {
        #pragma unroll 8
        for (int c = 0; c < CQ; c++)
            ob[(size_t)c * HW] = qb[(size_t)c * HW] * iq + ab[(size_t)c * HW] * ia;
    }
}

// ---------------- launch ------------------------------------------------------
extern "C" void kernel_launch(void* const* d_in, const int* in_sizes, int n_in,
                              void* d_out, int out_size) {
    const float *fq3 = 0, *fs3 = 0, *fq4 = 0, *fs4 = 0, *f_q = 0, *f_s = 0;
    for (int i = 0; i < n_in; i++) {
        const float* p = (const float*)d_in[i];
        int sz = in_sizes[i];
        if (sz == SZ3)      { if (!fq3) fq3 = p; else fs3 = p; }
        else if (sz == SZ4) { if (!fq4) fq4 = p; else fs4 = p; }
        else if (sz == SZQ) { if (!f_q) f_q = p; else f_s = p; }
    }
    float* out = (float*)d_out;

    // TRUE device addresses (host shadow symbols are ATS-dereferenceable on
    // GB300 -> silent zero-data bug if passed directly).
    void *pAh, *pBh, *pAttnH, *pVh, *pCorr, *pAttP;
    cudaGetSymbolAddress(&pAh, g_Ah);
    cudaGetSymbolAddress(&pBh, g_Bh);
    cudaGetSymbolAddress(&pAttnH, g_attnH);
    cudaGetSymbolAddress(&pVh, g_Vh);
    cudaGetSymbolAddress(&pCorr, g_corr);
    cudaGetSymbolAddress(&pAttP, g_attP);

    cudaFuncSetAttribute(gemm_h, cudaFuncAttributeMaxDynamicSharedMemorySize, GEMM_SMEM);

    norms4_kernel<<<dim3(114, 2, 4), 256>>>(fq4, fs4, C4, 0);
    norms4_kernel<<<dim3(114, 2, 4), 256>>>(fq3, fs3, C3, 2);

    transpose_kernel<<<dim3(113, C4 / 64, NB), 256>>>(fq4, C4, 0,  0, 0);
    transpose_kernel<<<dim3(113, C4 / 64, NB), 256>>>(fs4, C4, 0,  1, 1);
    transpose_kernel<<<dim3(113, C3 / 64, NB), 256>>>(fq3, C3, C4, 0, 2);
    transpose_kernel<<<dim3(113, C3 / 64, NB), 256>>>(fs3, C3, C4, 1, 3);

    vprep_kernel<<<(NB * CQ * KP + 255) / 256, 256>>>(f_s);

    // corr logits (x10 = 0.5 mean * 20 temp folded into epilogue)
    gemm_h<<<dim3(29, 29, NB), 256, GEMM_SMEM>>>(
        (const __half*)pAh, (const __half*)pBh, (float*)pCorr,
        CK, CK / 64, HW, HW,
        (size_t)HW * CK, (size_t)HW * CK, (size_t)HW * HW, 10.0f, 1);

    softmax_kernel<<<NB * HW, 256>>>();

    // attn GEMM with split-K=2: partials into g_attP, then reduce
    gemm_h<<<dim3(29, 2, NB * 2), 256, GEMM_SMEM>>>(
        (const __half*)pVh, (const __half*)pAttnH, (float*)pAttP,
        KP, KP / 64, CQ, HW,
        (size_t)CQ * KP, (size_t)HW * KP, (size_t)CQ * HW, 1.0f, 2);
    att_reduce_kernel<<<(SZQ / 4 + 255) / 256, 256>>>();

    int writeAtt = (out_size >= 2 * SZQ) ? 1 : 0;
    combine_kernel<<<29, 256>>>(f_q, out, out + SZQ, writeAtt);
}